// round 4
// baseline (speedup 1.0000x reference)
#include <cuda_runtime.h>
#include <math.h>

#define SEQ   512
#define BATCH 64
#define INDIM 1024
#define HDIM  1024
#define GDIM  4096   // 4*H

// Scratch
__device__ float g_xproj[(size_t)SEQ * BATCH * GDIM];   // 512 MB
__device__ float g_c[BATCH * HDIM];
__device__ float g_whi[(size_t)GDIM * HDIM];            // tf32-hi of W_hh
__device__ float g_wlo[(size_t)GDIM * HDIM];            // tf32 of (W - hi)
__device__ float g_hhi[2][BATCH * HDIM];                // parity double-buffer
__device__ float g_hlo[2][BATCH * HDIM];

typedef unsigned int u32;

__device__ __forceinline__ float tf32_rna(float a) {
    u32 b;
    asm("cvt.rna.tf32.f32 %0, %1;" : "=r"(b) : "f"(a));
    return __uint_as_float(b);
}

// m16n8k8 tf32 mma: D += A*B  (fragments per PTX ISA)
__device__ __forceinline__ void mma8(float& d0, float& d1, float& d2, float& d3,
                                     float a0, float a1, float a2, float a3,
                                     float b0, float b1) {
    asm volatile(
        "mma.sync.aligned.m16n8k8.row.col.f32.tf32.tf32.f32 "
        "{%0,%1,%2,%3}, {%4,%5,%6,%7}, {%8,%9}, {%0,%1,%2,%3};"
        : "+f"(d0), "+f"(d1), "+f"(d2), "+f"(d3)
        : "r"(__float_as_uint(a0)), "r"(__float_as_uint(a1)),
          "r"(__float_as_uint(a2)), "r"(__float_as_uint(a3)),
          "r"(__float_as_uint(b0)), "r"(__float_as_uint(b1)));
}

// Permuted k-offset within a chunk: pairs (k, k+4) adjacent so fragment loads
// are single LDS.64: p(k) = (k/8)*8 + (k%4)*2 + ((k/4)%2)
__device__ __forceinline__ int permk(int k) {
    return ((k >> 3) << 3) + ((k & 3) << 1) + ((k >> 2) & 1);
}

__device__ __forceinline__ float sigmoidf_(float x) {
    return 1.f / (1.f + expf(-x));
}

// ---------------------------------------------------------------------------
// One-time prep kernels
// ---------------------------------------------------------------------------
__global__ void split_w_kernel(const float* __restrict__ W) {
    size_t i = (size_t)blockIdx.x * blockDim.x + threadIdx.x;  // 4M threads
    float v = W[i];
    float h = tf32_rna(v);
    g_whi[i] = h;
    g_wlo[i] = tf32_rna(v - h);
}

__global__ void init_state_kernel(const float* __restrict__ h0,
                                  const float* __restrict__ c0) {
    int i = blockIdx.x * blockDim.x + threadIdx.x;  // 65536
    float h = h0[i];
    float hh = tf32_rna(h);
    g_hhi[0][i] = hh;
    g_hlo[0][i] = tf32_rna(h - hh);
    g_c[i] = c0[i];
}

// ---------------------------------------------------------------------------
// Kernel 1: x_proj = x @ W_ih^T + (b_ih + b_hh)   [HMMA tf32, 3-term split]
// A (32768 x 1024), W (4096 x 1024), K-major. Tile: M=128, N=64, Kchunk=32.
// 256 threads; warp w -> region (rm = w>>1 of 4, rn = w&1 of 2), each 32x32
// = 2 m-tiles(16) x 4 n-tiles(8).
// ---------------------------------------------------------------------------
#define XST 40   // row stride (floats); 40 % 32 == 8 -> conflict-free frags
#define XSMEM ((128 * XST * 2 + 64 * XST * 2) * 4)   // 61440 B

__global__ __launch_bounds__(256) void xproj_tc_kernel(
    const float* __restrict__ A, const float* __restrict__ W,
    const float* __restrict__ b1, const float* __restrict__ b2)
{
    extern __shared__ float sm[];
    float* Ahi = sm;                     // 128 x 40
    float* Alo = Ahi + 128 * XST;
    float* Bhi = Alo + 128 * XST;        // 64 x 40
    float* Blo = Bhi + 64 * XST;

    const int tid = threadIdx.x;
    const int w = tid >> 5, lane = tid & 31;
    const int g = lane >> 2, t = lane & 3;
    const int rm = w >> 1, rn = w & 1;
    const int n0 = blockIdx.x * 64;
    const int m0 = blockIdx.y * 128;

    float acc[2][4][4];
#pragma unroll
    for (int mt = 0; mt < 2; mt++)
#pragma unroll
        for (int nt = 0; nt < 4; nt++)
#pragma unroll
            for (int e = 0; e < 4; e++) acc[mt][nt][e] = 0.f;

    for (int k0 = 0; k0 < INDIM; k0 += 32) {
        // Stage A: 128x32, split hi/lo, permuted scatter
#pragma unroll
        for (int l = 0; l < 4; l++) {
            int idx = tid + l * 256;
            int r = idx >> 3, q = idx & 7;
            float4 v = *reinterpret_cast<const float4*>(
                A + (size_t)(m0 + r) * INDIM + k0 + q * 4);
            float vals[4] = {v.x, v.y, v.z, v.w};
#pragma unroll
            for (int e = 0; e < 4; e++) {
                int p = permk(q * 4 + e);
                float hv = tf32_rna(vals[e]);
                Ahi[r * XST + p] = hv;
                Alo[r * XST + p] = tf32_rna(vals[e] - hv);
            }
        }
        // Stage B (W rows): 64x32
#pragma unroll
        for (int l = 0; l < 2; l++) {
            int idx = tid + l * 256;
            int r = idx >> 3, q = idx & 7;
            float4 v = *reinterpret_cast<const float4*>(
                W + (size_t)(n0 + r) * INDIM + k0 + q * 4);
            float vals[4] = {v.x, v.y, v.z, v.w};
#pragma unroll
            for (int e = 0; e < 4; e++) {
                int p = permk(q * 4 + e);
                float hv = tf32_rna(vals[e]);
                Bhi[r * XST + p] = hv;
                Blo[r * XST + p] = tf32_rna(vals[e] - hv);
            }
        }
        __syncthreads();

#pragma unroll
        for (int ks = 0; ks < 4; ks++) {
            int ko = ks * 8 + 2 * t;
            float2 axh[2], ayh[2], axl[2], ayl[2];
#pragma unroll
            for (int mt = 0; mt < 2; mt++) {
                int ar = rm * 32 + mt * 16 + g;
                axh[mt] = *reinterpret_cast<const float2*>(&Ahi[ar * XST + ko]);
                ayh[mt] = *reinterpret_cast<const float2*>(&Ahi[(ar + 8) * XST + ko]);
                axl[mt] = *reinterpret_cast<const float2*>(&Alo[ar * XST + ko]);
                ayl[mt] = *reinterpret_cast<const float2*>(&Alo[(ar + 8) * XST + ko]);
            }
#pragma unroll
            for (int nt = 0; nt < 4; nt++) {
                int nr = rn * 32 + nt * 8 + g;
                float2 bh = *reinterpret_cast<const float2*>(&Bhi[nr * XST + ko]);
                float2 bl = *reinterpret_cast<const float2*>(&Blo[nr * XST + ko]);
#pragma unroll
                for (int mt = 0; mt < 2; mt++) {
                    float* d = acc[mt][nt];
                    mma8(d[0], d[1], d[2], d[3],
                         axh[mt].x, ayh[mt].x, axh[mt].y, ayh[mt].y, bh.x, bh.y);
                    mma8(d[0], d[1], d[2], d[3],
                         axl[mt].x, ayl[mt].x, axl[mt].y, ayl[mt].y, bh.x, bh.y);
                    mma8(d[0], d[1], d[2], d[3],
                         axh[mt].x, ayh[mt].x, axh[mt].y, ayh[mt].y, bl.x, bl.y);
                }
            }
        }
        __syncthreads();
    }

    // Epilogue: + bias, store float2 pairs
#pragma unroll
    for (int mt = 0; mt < 2; mt++) {
        int row = m0 + rm * 32 + mt * 16 + g;
#pragma unroll
        for (int nt = 0; nt < 4; nt++) {
            int col = n0 + rn * 32 + nt * 8 + 2 * t;
            float bv0 = b1[col] + b2[col];
            float bv1 = b1[col + 1] + b2[col + 1];
            float2 v0 = make_float2(acc[mt][nt][0] + bv0, acc[mt][nt][1] + bv1);
            float2 v1 = make_float2(acc[mt][nt][2] + bv0, acc[mt][nt][3] + bv1);
            *reinterpret_cast<float2*>(g_xproj + (size_t)row * GDIM + col) = v0;
            *reinterpret_cast<float2*>(g_xproj + (size_t)(row + 8) * GDIM + col) = v1;
        }
    }
}

// ---------------------------------------------------------------------------
// Kernel 2: LSTM timestep [HMMA tf32, 3-term]. 128 CTAs x 256 thr.
// CTA owns 8 hidden cols jt..jt+8 -> 32 gate cols {j, H+j, 2H+j, 3H+j}.
// GEMM M=64(batch) x N=32 x K=1024 (chunks of 64).
// Warp w: mt = w&3 (16 batch rows), nh = w>>2 (16 gate cols = 2 n-tiles).
// W hi/lo from pre-split scratch; h hi/lo from parity buffers (written by
// previous step's epilogue).
// ---------------------------------------------------------------------------
#define SST 72   // 72 % 32 == 8 -> conflict-free frags
#define SSMEM ((64 * SST * 2 + 32 * SST * 2) * 4)   // 55296 B

__global__ __launch_bounds__(256) void lstm_step_kernel(
    float* __restrict__ out, int step)
{
    extern __shared__ float sm[];
    float* Ahi = sm;                    // 64 x 72
    float* Alo = Ahi + 64 * SST;
    float* Bhi = Alo + 64 * SST;        // 32 x 72
    float* Blo = Bhi + 32 * SST;

    const int tid = threadIdx.x;
    const int w = tid >> 5, lane = tid & 31;
    const int g = lane >> 2, t = lane & 3;
    const int mt = w & 3, nh = w >> 2;
    const int jt = blockIdx.x * 8;
    const int rp = step & 1;            // read parity

    const float* hhi = g_hhi[rp];
    const float* hlo = g_hlo[rp];
    float* whi_n = g_hhi[rp ^ 1];
    float* wlo_n = g_hlo[rp ^ 1];

    float acc[2][4];
#pragma unroll
    for (int nt = 0; nt < 2; nt++)
#pragma unroll
        for (int e = 0; e < 4; e++) acc[nt][e] = 0.f;

    for (int k0 = 0; k0 < HDIM; k0 += 64) {
        // Stage h hi/lo: 64x64 each, permuted
#pragma unroll
        for (int l = 0; l < 4; l++) {
            int idx = tid + l * 256;
            int r = idx >> 4, q = idx & 15;
            float4 vh = *reinterpret_cast<const float4*>(hhi + r * HDIM + k0 + q * 4);
            float4 vl = *reinterpret_cast<const float4*>(hlo + r * HDIM + k0 + q * 4);
            float hs[4] = {vh.x, vh.y, vh.z, vh.w};
            float ls[4] = {vl.x, vl.y, vl.z, vl.w};
#pragma unroll
            for (int e = 0; e < 4; e++) {
                int p = permk(q * 4 + e);
                Ahi[r * SST + p] = hs[e];
                Alo[r * SST + p] = ls[e];
            }
        }
        // Stage W hi/lo: 32 gate-rows x 64
#pragma unroll
        for (int l = 0; l < 2; l++) {
            int idx = tid + l * 256;
            int r = idx >> 4, q = idx & 15;
            int grow = (r >> 3) * HDIM + jt + (r & 7);
            float4 vh = *reinterpret_cast<const float4*>(
                g_whi + (size_t)grow * HDIM + k0 + q * 4);
            float4 vl = *reinterpret_cast<const float4*>(
                g_wlo + (size_t)grow * HDIM + k0 + q * 4);
            float hs[4] = {vh.x, vh.y, vh.z, vh.w};
            float ls[4] = {vl.x, vl.y, vl.z, vl.w};
#pragma unroll
            for (int e = 0; e < 4; e++) {
                int p = permk(q * 4 + e);
                Bhi[r * SST + p] = hs[e];
                Blo[r * SST + p] = ls[e];
            }
        }
        __syncthreads();

        int ar = mt * 16 + g;
#pragma unroll
        for (int ks = 0; ks < 8; ks++) {
            int ko = ks * 8 + 2 * t;
            float2 axh = *reinterpret_cast<const float2*>(&Ahi[ar * SST + ko]);
            float2 ayh = *reinterpret_cast<const float2*>(&Ahi[(ar + 8) * SST + ko]);
            float2 axl = *reinterpret_cast<const float2*>(&Alo[ar * SST + ko]);
            float2 ayl = *reinterpret_cast<const float2*>(&Alo[(ar + 8) * SST + ko]);
#pragma unroll
            for (int nt = 0; nt < 2; nt++) {
                int nr = nh * 16 + nt * 8 + g;
                float2 bh = *reinterpret_cast<const float2*>(&Bhi[nr * SST + ko]);
                float2 bl = *reinterpret_cast<const float2*>(&Blo[nr * SST + ko]);
                float* d = acc[nt];
                mma8(d[0], d[1], d[2], d[3], axh.x, ayh.x, axh.y, ayh.y, bh.x, bh.y);
                mma8(d[0], d[1], d[2], d[3], axl.x, ayl.x, axl.y, ayl.y, bh.x, bh.y);
                mma8(d[0], d[1], d[2], d[3], axh.x, ayh.x, axh.y, ayh.y, bl.x, bl.y);
            }
        }
        __syncthreads();
    }

    // Gates (+ xproj) into smem exchange buffer (overlays Ahi; stride 33)
    float* gsm = Ahi;
#pragma unroll
    for (int nt = 0; nt < 2; nt++) {
        int c0 = nh * 16 + nt * 8 + 2 * t;
        int b0 = mt * 16 + g;
        int gc0 = (c0 >> 3) * HDIM + jt + (c0 & 7);
        int gc1 = gc0 + 1;   // c0 even, c0+1 same gate group
        const float* xp0 = g_xproj + ((size_t)b0 * SEQ + step) * GDIM;
        const float* xp1 = g_xproj + ((size_t)(b0 + 8) * SEQ + step) * GDIM;
        gsm[b0 * 33 + c0]           = acc[nt][0] + xp0[gc0];
        gsm[b0 * 33 + c0 + 1]       = acc[nt][1] + xp0[gc1];
        gsm[(b0 + 8) * 33 + c0]     = acc[nt][2] + xp1[gc0];
        gsm[(b0 + 8) * 33 + c0 + 1] = acc[nt][3] + xp1[gc1];
    }
    __syncthreads();

    // Pointwise update: 512 elems, 2 per thread. Also write split h for next step.
#pragma unroll
    for (int l = 0; l < 2; l++) {
        int pid = tid + l * 256;
        int b = pid >> 3, jj = pid & 7, j = jt + jj;
        float ig = gsm[b * 33 + jj];
        float fg = gsm[b * 33 + 8 + jj];
        float gg = gsm[b * 33 + 16 + jj];
        float og = gsm[b * 33 + 24 + jj];
        float cold = g_c[b * HDIM + j];
        float cn = sigmoidf_(fg) * cold + sigmoidf_(ig) * tanhf(gg);
        float h = sigmoidf_(og) * tanhf(cn);
        g_c[b * HDIM + j] = cn;
        out[(size_t)b * SEQ * HDIM + (size_t)step * HDIM + j] = h;
        float hh = tf32_rna(h);
        whi_n[b * HDIM + j] = hh;
        wlo_n[b * HDIM + j] = tf32_rna(h - hh);
    }
}

// ---------------------------------------------------------------------------
// Finalize: append (h_final, c_final)
// ---------------------------------------------------------------------------
__global__ void finalize_kernel(const float* __restrict__ out,
                                float* __restrict__ tail) {
    int i = blockIdx.x * blockDim.x + threadIdx.x;   // 0..65535
    int b = i >> 10, j = i & 1023;
    tail[i] = out[(size_t)b * SEQ * HDIM + (size_t)(SEQ - 1) * HDIM + j];
    tail[BATCH * HDIM + i] = g_c[i];
}

// ---------------------------------------------------------------------------
// Launch
// ---------------------------------------------------------------------------
extern "C" void kernel_launch(void* const* d_in, const int* in_sizes, int n_in,
                              void* d_out, int out_size) {
    const float* inp  = (const float*)d_in[0];
    const float* h0   = (const float*)d_in[1];
    const float* c0   = (const float*)d_in[2];
    const float* W_ih = (const float*)d_in[3];
    const float* W_hh = (const float*)d_in[4];
    const float* b_ih = (const float*)d_in[5];
    const float* b_hh = (const float*)d_in[6];
    float* out = (float*)d_out;

    cudaFuncSetAttribute(xproj_tc_kernel,
                         cudaFuncAttributeMaxDynamicSharedMemorySize, XSMEM);
    cudaFuncSetAttribute(lstm_step_kernel,
                         cudaFuncAttributeMaxDynamicSharedMemorySize, SSMEM);

    split_w_kernel<<<GDIM * HDIM / 1024, 1024>>>(W_hh);
    init_state_kernel<<<64, 1024>>>(h0, c0);

    dim3 gx(GDIM / 64, (SEQ * BATCH) / 128);
    xproj_tc_kernel<<<gx, 256, XSMEM>>>(inp, W_ih, b_ih, b_hh);

    for (int t = 0; t < SEQ; t++) {
        lstm_step_kernel<<<128, 256, SSMEM>>>(out, t);
    }

    if (out_size >= SEQ * BATCH * HDIM + 2 * BATCH * HDIM) {
        finalize_kernel<<<64, 1024>>>(out, out + (size_t)SEQ * BATCH * HDIM);
    }
}

// round 5
// speedup vs baseline: 1.3205x; 1.3205x over previous
#include <cuda_runtime.h>
#include <math.h>

#define SEQ   512
#define BATCH 64
#define INDIM 1024
#define HDIM  1024
#define GDIM  4096   // 4*H

typedef unsigned int u32;

// ---------------------------------------------------------------------------
// Gmem scratch (staged, pre-split, pre-permuted, padded layouts)
// ---------------------------------------------------------------------------
__device__ float g_xproj[(size_t)SEQ * BATCH * GDIM];              // 512 MB
__device__ float g_c[BATCH * HDIM];

// A (inp) staged for xproj: per (mtile 0..255, ck 0..31): [hi 128x36][lo 128x36]
#define ABLK (128 * 36 * 2)            // 9216 floats
__device__ float g_astage[(size_t)256 * 32 * ABLK];                // 288 MB

// W_ih staged: per (ntile 0..63, ck 0..31): [hi 64x36][lo 64x36]
#define WIBLK (64 * 36 * 2)            // 4608 floats
__device__ float g_wihstage[(size_t)64 * 32 * WIBLK];              // 36 MB

// W_hh staged: per (ct 0..127, ck 0..15): [hi 32x68][lo 32x68]
#define WHBLK (32 * 68 * 2)            // 4352 floats
__device__ float g_whhstage[(size_t)128 * 16 * WHBLK];             // 34 MB

// h staged (parity double buffer): per (par, ck 0..15): [hi 64x68][lo 64x68]
#define HBLK (64 * 68 * 2)             // 8704 floats
#define HPAR (16 * HBLK)
__device__ float g_hstage[2 * HPAR];                               // ~1.1 MB

// ---------------------------------------------------------------------------
// Helpers
// ---------------------------------------------------------------------------
__device__ __forceinline__ float tf32_rna(float a) {
    u32 b;
    asm("cvt.rna.tf32.f32 %0, %1;" : "=r"(b) : "f"(a));
    return __uint_as_float(b);
}

// m16n8k8 tf32 mma
__device__ __forceinline__ void mma8(float& d0, float& d1, float& d2, float& d3,
                                     float a0, float a1, float a2, float a3,
                                     float b0, float b1) {
    asm volatile(
        "mma.sync.aligned.m16n8k8.row.col.f32.tf32.tf32.f32 "
        "{%0,%1,%2,%3}, {%4,%5,%6,%7}, {%8,%9}, {%0,%1,%2,%3};"
        : "+f"(d0), "+f"(d1), "+f"(d2), "+f"(d3)
        : "r"(__float_as_uint(a0)), "r"(__float_as_uint(a1)),
          "r"(__float_as_uint(a2)), "r"(__float_as_uint(a3)),
          "r"(__float_as_uint(b0)), "r"(__float_as_uint(b1)));
}

// pair (k, k+4) adjacent within each 8-group -> fragment loads are LDS.64
__device__ __forceinline__ int permk(int k) {
    return ((k >> 3) << 3) + ((k & 3) << 1) + ((k >> 2) & 1);
}

__device__ __forceinline__ float sigmoidf_(float x) {
    return 1.f / (1.f + expf(-x));
}

__device__ __forceinline__ u32 smem_u32(const void* p) {
    u32 a;
    asm("{ .reg .u64 t; cvta.to.shared.u64 t, %1; cvt.u32.u64 %0, t; }"
        : "=r"(a) : "l"(p));
    return a;
}

__device__ __forceinline__ void cpa16(u32 dst, const float4* src) {
    asm volatile("cp.async.cg.shared.global [%0], [%1], 16;"
                 :: "r"(dst), "l"(src));
}
#define CPA_COMMIT() asm volatile("cp.async.commit_group;" ::: "memory")
#define CPA_WAIT1()  asm volatile("cp.async.wait_group 1;" ::: "memory")
#define CPA_WAIT0()  asm volatile("cp.async.wait_group 0;" ::: "memory")

// ---------------------------------------------------------------------------
// One-time split/permute kernels
// ---------------------------------------------------------------------------
__global__ void split_a_kernel(const float* __restrict__ A) {
    size_t idx = (size_t)blockIdx.x * 1024 + threadIdx.x;   // 33.5M
    int m = (int)(idx >> 10), k = (int)(idx & 1023);
    float v = A[idx];
    float hi = tf32_rna(v);
    float lo = tf32_rna(v - hi);
    int mtile = m >> 7, r = m & 127, ck = k >> 5, kk = k & 31;
    float* dst = g_astage + (size_t)(mtile * 32 + ck) * ABLK + r * 36 + permk(kk);
    dst[0] = hi;
    dst[128 * 36] = lo;
}

__global__ void split_wih_kernel(const float* __restrict__ W) {
    int nt = blockIdx.x >> 5, ck = blockIdx.x & 31;   // 2048 blocks
    float* base = g_wihstage + (size_t)blockIdx.x * WIBLK;
#pragma unroll
    for (int l = 0; l < 4; l++) {
        int e = threadIdx.x + l * 512;                 // 64r x 32k
        int r = e >> 5, k = e & 31;
        float v = W[(size_t)(nt * 64 + r) * INDIM + ck * 32 + k];
        float hi = tf32_rna(v);
        base[r * 36 + permk(k)] = hi;
        base[64 * 36 + r * 36 + permk(k)] = tf32_rna(v - hi);
    }
}

__global__ void split_whh_kernel(const float* __restrict__ W) {
    int ct = blockIdx.x >> 4, ck = blockIdx.x & 15;   // 2048 blocks
    float* base = g_whhstage + (size_t)blockIdx.x * WHBLK;
#pragma unroll
    for (int l = 0; l < 4; l++) {
        int e = threadIdx.x + l * 512;                 // 32r x 64k
        int r = e >> 6, k = e & 63;
        int grow = (r >> 3) * HDIM + ct * 8 + (r & 7);
        float v = W[(size_t)grow * HDIM + ck * 64 + k];
        float hi = tf32_rna(v);
        base[r * 68 + permk(k)] = hi;
        base[32 * 68 + r * 68 + permk(k)] = tf32_rna(v - hi);
    }
}

__global__ void init_state_kernel(const float* __restrict__ h0,
                                  const float* __restrict__ c0) {
    int i = blockIdx.x * blockDim.x + threadIdx.x;  // 65536
    int b = i >> 10, j = i & 1023;
    float h = h0[i];
    float hi = tf32_rna(h);
    int ck = j >> 6, p = permk(j & 63);
    float* hs = g_hstage + (size_t)ck * HBLK;
    hs[b * 68 + p] = hi;
    hs[64 * 68 + b * 68 + p] = tf32_rna(h - hi);
    g_c[i] = c0[i];
}

// ---------------------------------------------------------------------------
// Kernel 1: x_proj = A @ W_ih^T + bias.  cp.async double-buffered HMMA.
// Tile M=128, N=64, Kchunk=32; 256 threads; warp w: rm=w>>1 (4), rn=w&1 (2).
// smem buffer (floats): Ahi 0 (128x36), Alo 4608, Bhi 9216 (64x36), Blo 11520.
// ---------------------------------------------------------------------------
#define XBUF 13824                       // floats per buffer
#define XSMEM (2 * XBUF * 4)             // 110592 B

__global__ __launch_bounds__(256) void xproj_tc_kernel(
    const float* __restrict__ b1, const float* __restrict__ b2)
{
    extern __shared__ float sm[];
    const u32 sbase = smem_u32(sm);
    const int tid = threadIdx.x;
    const int w = tid >> 5, lane = tid & 31;
    const int g = lane >> 2, t = lane & 3;
    const int rm = w >> 1, rn = w & 1;
    const int ntile = blockIdx.x, mtile = blockIdx.y;

    const float4* asrc = reinterpret_cast<const float4*>(
        g_astage + (size_t)(mtile * 32) * ABLK);
    const float4* wsrc = reinterpret_cast<const float4*>(
        g_wihstage + (size_t)(ntile * 32) * WIBLK);

    // stage chunk ck into buf
    auto stage = [&](int ck, int buf) {
        u32 d = sbase + (u32)buf * (XBUF * 4);
        const float4* a = asrc + (size_t)ck * (ABLK / 4);
        const float4* ww = wsrc + (size_t)ck * (WIBLK / 4);
        for (int i = tid; i < ABLK / 4; i += 256) cpa16(d + i * 16, a + i);
        for (int i = tid; i < WIBLK / 4; i += 256)
            cpa16(d + ABLK * 4 + i * 16, ww + i);
    };

    float acc[2][4][4];
#pragma unroll
    for (int mt = 0; mt < 2; mt++)
#pragma unroll
        for (int nt = 0; nt < 4; nt++)
#pragma unroll
            for (int e = 0; e < 4; e++) acc[mt][nt][e] = 0.f;

    stage(0, 0);
    CPA_COMMIT();

    for (int ck = 0; ck < 32; ck++) {
        if (ck < 31) { stage(ck + 1, (ck + 1) & 1); CPA_COMMIT(); CPA_WAIT1(); }
        else CPA_WAIT0();
        __syncthreads();

        const float* Ahi = sm + (ck & 1) * XBUF;
        const float* Alo = Ahi + 4608;
        const float* Bhi = Ahi + 9216;
        const float* Blo = Ahi + 11520;

#pragma unroll
        for (int ks = 0; ks < 4; ks++) {
            int ko = ks * 8 + 2 * t;
            float2 axh[2], ayh[2], axl[2], ayl[2];
#pragma unroll
            for (int mt = 0; mt < 2; mt++) {
                int ar = rm * 32 + mt * 16 + g;
                axh[mt] = *reinterpret_cast<const float2*>(&Ahi[ar * 36 + ko]);
                ayh[mt] = *reinterpret_cast<const float2*>(&Ahi[(ar + 8) * 36 + ko]);
                axl[mt] = *reinterpret_cast<const float2*>(&Alo[ar * 36 + ko]);
                ayl[mt] = *reinterpret_cast<const float2*>(&Alo[(ar + 8) * 36 + ko]);
            }
#pragma unroll
            for (int nt = 0; nt < 4; nt++) {
                int nr = rn * 32 + nt * 8 + g;
                float2 bh = *reinterpret_cast<const float2*>(&Bhi[nr * 36 + ko]);
                float2 bl = *reinterpret_cast<const float2*>(&Blo[nr * 36 + ko]);
#pragma unroll
                for (int mt = 0; mt < 2; mt++) {
                    float* d = acc[mt][nt];
                    mma8(d[0], d[1], d[2], d[3],
                         axh[mt].x, ayh[mt].x, axh[mt].y, ayh[mt].y, bh.x, bh.y);
                    mma8(d[0], d[1], d[2], d[3],
                         axl[mt].x, ayl[mt].x, axl[mt].y, ayl[mt].y, bh.x, bh.y);
                    mma8(d[0], d[1], d[2], d[3],
                         axh[mt].x, ayh[mt].x, axh[mt].y, ayh[mt].y, bl.x, bl.y);
                }
            }
        }
        __syncthreads();
    }

    const int m0 = mtile * 128, n0 = ntile * 64;
#pragma unroll
    for (int mt = 0; mt < 2; mt++) {
        int row = m0 + rm * 32 + mt * 16 + g;
#pragma unroll
        for (int nt = 0; nt < 4; nt++) {
            int col = n0 + rn * 32 + nt * 8 + 2 * t;
            float bv0 = b1[col] + b2[col];
            float bv1 = b1[col + 1] + b2[col + 1];
            float2 v0 = make_float2(acc[mt][nt][0] + bv0, acc[mt][nt][1] + bv1);
            float2 v1 = make_float2(acc[mt][nt][2] + bv0, acc[mt][nt][3] + bv1);
            *reinterpret_cast<float2*>(g_xproj + (size_t)row * GDIM + col) = v0;
            *reinterpret_cast<float2*>(g_xproj + (size_t)(row + 8) * GDIM + col) = v1;
        }
    }
}

// ---------------------------------------------------------------------------
// Kernel 2: LSTM step. 128 CTAs x 256 thr. CTA ct owns 8 hidden cols
// jt=ct*8 -> 32 gate cols. GEMM M=64 x N=32 x K=1024, Kchunk=64,
// cp.async double-buffered. Warp w: mt=w&3 (16 batch rows), nh=w>>2 (16 cols).
// smem buffer (floats): Ahi 0 (64x68), Alo 4352, Bhi 8704 (32x68), Blo 10880.
// ---------------------------------------------------------------------------
#define SBUF 13056                       // floats per buffer
#define SSMEM (2 * SBUF * 4)             // 104448 B

__global__ __launch_bounds__(256) void lstm_step_kernel(
    float* __restrict__ out, int step)
{
    extern __shared__ float sm[];
    const u32 sbase = smem_u32(sm);
    const int tid = threadIdx.x;
    const int w = tid >> 5, lane = tid & 31;
    const int g = lane >> 2, t = lane & 3;
    const int mt = w & 3, nh = w >> 2;
    const int ct = blockIdx.x, jt = ct * 8;
    const int rp = step & 1;

    const float4* hsrc = reinterpret_cast<const float4*>(g_hstage + (size_t)rp * HPAR);
    const float4* wsrc = reinterpret_cast<const float4*>(
        g_whhstage + (size_t)(ct * 16) * WHBLK);
    float* hdst = g_hstage + (size_t)(rp ^ 1) * HPAR;

    auto stage = [&](int ck, int buf) {
        u32 d = sbase + (u32)buf * (SBUF * 4);
        const float4* h = hsrc + (size_t)ck * (HBLK / 4);
        const float4* ww = wsrc + (size_t)ck * (WHBLK / 4);
        for (int i = tid; i < HBLK / 4; i += 256) cpa16(d + i * 16, h + i);
        for (int i = tid; i < WHBLK / 4; i += 256)
            cpa16(d + HBLK * 4 + i * 16, ww + i);
    };

    float acc[2][4];
#pragma unroll
    for (int nt = 0; nt < 2; nt++)
#pragma unroll
        for (int e = 0; e < 4; e++) acc[nt][e] = 0.f;

    stage(0, 0);
    CPA_COMMIT();

    for (int ck = 0; ck < 16; ck++) {
        if (ck < 15) { stage(ck + 1, (ck + 1) & 1); CPA_COMMIT(); CPA_WAIT1(); }
        else CPA_WAIT0();
        __syncthreads();

        const float* Ahi = sm + (ck & 1) * SBUF;
        const float* Alo = Ahi + 4352;
        const float* Bhi = Ahi + 8704;
        const float* Blo = Ahi + 10880;

        int ar = mt * 16 + g;
#pragma unroll
        for (int ks = 0; ks < 8; ks++) {
            int ko = ks * 8 + 2 * t;
            float2 axh = *reinterpret_cast<const float2*>(&Ahi[ar * 68 + ko]);
            float2 ayh = *reinterpret_cast<const float2*>(&Ahi[(ar + 8) * 68 + ko]);
            float2 axl = *reinterpret_cast<const float2*>(&Alo[ar * 68 + ko]);
            float2 ayl = *reinterpret_cast<const float2*>(&Alo[(ar + 8) * 68 + ko]);
#pragma unroll
            for (int nt = 0; nt < 2; nt++) {
                int nr = nh * 16 + nt * 8 + g;
                float2 bh = *reinterpret_cast<const float2*>(&Bhi[nr * 68 + ko]);
                float2 bl = *reinterpret_cast<const float2*>(&Blo[nr * 68 + ko]);
                float* d = acc[nt];
                mma8(d[0], d[1], d[2], d[3], axh.x, ayh.x, axh.y, ayh.y, bh.x, bh.y);
                mma8(d[0], d[1], d[2], d[3], axl.x, ayl.x, axl.y, ayl.y, bh.x, bh.y);
                mma8(d[0], d[1], d[2], d[3], axh.x, ayh.x, axh.y, ayh.y, bl.x, bl.y);
            }
        }
        __syncthreads();
    }

    // gate exchange (overlays buf0; 64x33 floats)
    float* gsm = sm;
#pragma unroll
    for (int nt = 0; nt < 2; nt++) {
        int c0 = nh * 16 + nt * 8 + 2 * t;
        int b0 = mt * 16 + g;
        int gc0 = (c0 >> 3) * HDIM + jt + (c0 & 7);
        const float* xp0 = g_xproj + ((size_t)b0 * SEQ + step) * GDIM;
        const float* xp1 = g_xproj + ((size_t)(b0 + 8) * SEQ + step) * GDIM;
        gsm[b0 * 33 + c0]           = acc[nt][0] + xp0[gc0];
        gsm[b0 * 33 + c0 + 1]       = acc[nt][1] + xp0[gc0 + 1];
        gsm[(b0 + 8) * 33 + c0]     = acc[nt][2] + xp1[gc0];
        gsm[(b0 + 8) * 33 + c0 + 1] = acc[nt][3] + xp1[gc0 + 1];
    }
    __syncthreads();

    // pointwise update + write next-step h stage
#pragma unroll
    for (int l = 0; l < 2; l++) {
        int pid = tid + l * 256;
        int b = pid >> 3, jj = pid & 7, j = jt + jj;
        float ig = gsm[b * 33 + jj];
        float fg = gsm[b * 33 + 8 + jj];
        float gg = gsm[b * 33 + 16 + jj];
        float og = gsm[b * 33 + 24 + jj];
        float cold = g_c[b * HDIM + j];
        float cn = sigmoidf_(fg) * cold + sigmoidf_(ig) * tanhf(gg);
        float h = sigmoidf_(og) * tanhf(cn);
        g_c[b * HDIM + j] = cn;
        out[(size_t)b * SEQ * HDIM + (size_t)step * HDIM + j] = h;
        float hi = tf32_rna(h);
        int ck = j >> 6, p = permk(j & 63);
        float* hs = hdst + (size_t)ck * HBLK;
        hs[b * 68 + p] = hi;
        hs[64 * 68 + b * 68 + p] = tf32_rna(h - hi);
    }
}

// ---------------------------------------------------------------------------
// Finalize
// ---------------------------------------------------------------------------
__global__ void finalize_kernel(const float* __restrict__ out,
                                float* __restrict__ tail) {
    int i = blockIdx.x * blockDim.x + threadIdx.x;   // 0..65535
    int b = i >> 10, j = i & 1023;
    tail[i] = out[(size_t)b * SEQ * HDIM + (size_t)(SEQ - 1) * HDIM + j];
    tail[BATCH * HDIM + i] = g_c[i];
}

// ---------------------------------------------------------------------------
// Launch
// ---------------------------------------------------------------------------
extern "C" void kernel_launch(void* const* d_in, const int* in_sizes, int n_in,
                              void* d_out, int out_size) {
    const float* inp  = (const float*)d_in[0];
    const float* h0   = (const float*)d_in[1];
    const float* c0   = (const float*)d_in[2];
    const float* W_ih = (const float*)d_in[3];
    const float* W_hh = (const float*)d_in[4];
    const float* b_ih = (const float*)d_in[5];
    const float* b_hh = (const float*)d_in[6];
    float* out = (float*)d_out;

    cudaFuncSetAttribute(xproj_tc_kernel,
                         cudaFuncAttributeMaxDynamicSharedMemorySize, XSMEM);
    cudaFuncSetAttribute(lstm_step_kernel,
                         cudaFuncAttributeMaxDynamicSharedMemorySize, SSMEM);

    split_a_kernel<<<SEQ * BATCH * INDIM / 1024, 1024>>>(inp);
    split_wih_kernel<<<2048, 512>>>(W_ih);
    split_whh_kernel<<<2048, 512>>>(W_hh);
    init_state_kernel<<<64, 1024>>>(h0, c0);

    dim3 gx(GDIM / 64, (SEQ * BATCH) / 128);
    xproj_tc_kernel<<<gx, 256, XSMEM>>>(b_ih, b_hh);

    for (int t = 0; t < SEQ; t++) {
        lstm_step_kernel<<<128, 256, SSMEM>>>(out, t);
    }

    if (out_size >= SEQ * BATCH * HDIM + 2 * BATCH * HDIM) {
        finalize_kernel<<<64, 1024>>>(out, out + (size_t)SEQ * BATCH * HDIM);
    }
}

// round 8
// speedup vs baseline: 1.5685x; 1.1878x over previous
#include <cuda_runtime.h>
#include <math.h>

#define SEQ   512
#define BATCH 64
#define INDIM 1024
#define HDIM  1024
#define GDIM  4096   // 4*H

typedef unsigned int u32;
typedef unsigned long long u64;

// ---------------------------------------------------------------------------
// Gmem scratch
// ---------------------------------------------------------------------------
__device__ float g_xproj[(size_t)SEQ * BATCH * GDIM];              // 512 MB

// A (inp) staged fp32, permuted: per (mtile 0..255, ck 0..31): 128x36
#define ABLK 4608
__device__ float g_astage[(size_t)256 * 32 * ABLK];                // 144 MB

// W_ih staged hi/lo: per (ntile 0..63, ck 0..31): [hi 64x36][lo 64x36]
#define WIBLK (64 * 36 * 2)
__device__ float g_wihstage[(size_t)64 * 32 * WIBLK];              // 36 MB

// W_hh staged hi/lo: per (ct 0..127, ck 0..15): [hi 32x68][lo 32x68]
#define WHBLK (32 * 68 * 2)
__device__ float g_whhstage[(size_t)128 * 16 * WHBLK];             // 34 MB

// h staged fp32 (parity double buffer): per (par, ck 0..15): 64x68
#define HBLK 4352
#define HPAR (16 * HBLK)
__device__ float g_hstage[2 * HPAR];

// Global barrier state (monotonic across graph replays; never reset)
__device__ u64 g_bar_count;
__device__ u64 g_bar_epoch;

// ---------------------------------------------------------------------------
// Helpers
// ---------------------------------------------------------------------------
// Truncation-based tf32 split: hi = trunc_tf32(v); lo = v - hi (exact).
__device__ __forceinline__ float trunc_tf32(float v) {
    return __uint_as_float(__float_as_uint(v) & 0xffffe000u);
}

__device__ __forceinline__ void mma8(float& d0, float& d1, float& d2, float& d3,
                                     float a0, float a1, float a2, float a3,
                                     float b0, float b1) {
    asm volatile(
        "mma.sync.aligned.m16n8k8.row.col.f32.tf32.tf32.f32 "
        "{%0,%1,%2,%3}, {%4,%5,%6,%7}, {%8,%9}, {%0,%1,%2,%3};"
        : "+f"(d0), "+f"(d1), "+f"(d2), "+f"(d3)
        : "r"(__float_as_uint(a0)), "r"(__float_as_uint(a1)),
          "r"(__float_as_uint(a2)), "r"(__float_as_uint(a3)),
          "r"(__float_as_uint(b0)), "r"(__float_as_uint(b1)));
}

// pair (k, k+4) adjacent within each 8-group -> fragment loads are LDS.64
__device__ __forceinline__ int permk(int k) {
    return ((k >> 3) << 3) + ((k & 3) << 1) + ((k >> 2) & 1);
}

__device__ __forceinline__ float sigmoidf_(float x) {
    return 1.f / (1.f + expf(-x));
}

__device__ __forceinline__ u32 smem_u32(const void* p) {
    u32 a;
    asm("{ .reg .u64 t; cvta.to.shared.u64 t, %1; cvt.u32.u64 %0, t; }"
        : "=r"(a) : "l"(p));
    return a;
}

__device__ __forceinline__ void cpa16(u32 dst, const float4* src) {
    asm volatile("cp.async.cg.shared.global [%0], [%1], 16;"
                 :: "r"(dst), "l"(src));
}
#define CPA_COMMIT() asm volatile("cp.async.commit_group;" ::: "memory")
#define CPA_WAIT1()  asm volatile("cp.async.wait_group 1;" ::: "memory")
#define CPA_WAIT0()  asm volatile("cp.async.wait_group 0;" ::: "memory")

// Grid-wide barrier: monotonic epoch, graph-replay safe.
__device__ __forceinline__ void gbar(u64 target) {
    __threadfence();
    __syncthreads();
    if (threadIdx.x == 0) {
        u64 arr;
        asm volatile("atom.acq_rel.gpu.global.add.u64 %0, [%1], 1;"
                     : "=l"(arr) : "l"(&g_bar_count) : "memory");
        arr += 1;
        if (arr == target * 128ull) {
            asm volatile("st.release.gpu.global.u64 [%0], %1;"
                         :: "l"(&g_bar_epoch), "l"(target) : "memory");
        } else {
            u64 v;
            for (;;) {
                asm volatile("ld.acquire.gpu.global.u64 %0, [%1];"
                             : "=l"(v) : "l"(&g_bar_epoch) : "memory");
                if (v >= target) break;
                __nanosleep(64);
            }
        }
    }
    __syncthreads();
}

// ---------------------------------------------------------------------------
// One-time prep kernels
// ---------------------------------------------------------------------------
__global__ void split_a_kernel(const float* __restrict__ A) {
    size_t idx = (size_t)blockIdx.x * 1024 + threadIdx.x;   // 33.5M
    int m = (int)(idx >> 10), k = (int)(idx & 1023);
    g_astage[(size_t)((m >> 7) * 32 + (k >> 5)) * ABLK
             + (m & 127) * 36 + permk(k & 31)] = A[idx];
}

__global__ void split_wih_kernel(const float* __restrict__ W) {
    int nt = blockIdx.x >> 5, ck = blockIdx.x & 31;   // 2048 blocks
    float* base = g_wihstage + (size_t)blockIdx.x * WIBLK;
#pragma unroll
    for (int l = 0; l < 4; l++) {
        int e = threadIdx.x + l * 512;                 // 64r x 32k
        int r = e >> 5, k = e & 31;
        float v = W[(size_t)(nt * 64 + r) * INDIM + ck * 32 + k];
        float hi = trunc_tf32(v);
        base[r * 36 + permk(k)] = hi;
        base[64 * 36 + r * 36 + permk(k)] = v - hi;
    }
}

__global__ void split_whh_kernel(const float* __restrict__ W) {
    int ct = blockIdx.x >> 4, ck = blockIdx.x & 15;   // 2048 blocks
    float* base = g_whhstage + (size_t)blockIdx.x * WHBLK;
#pragma unroll
    for (int l = 0; l < 4; l++) {
        int e = threadIdx.x + l * 512;                 // 32r x 64k
        int r = e >> 6, k = e & 63;
        int grow = (r >> 3) * HDIM + ct * 8 + (r & 7);
        float v = W[(size_t)grow * HDIM + ck * 64 + k];
        float hi = trunc_tf32(v);
        base[r * 68 + permk(k)] = hi;
        base[32 * 68 + r * 68 + permk(k)] = v - hi;
    }
}

__global__ void init_state_kernel(const float* __restrict__ h0) {
    int i = blockIdx.x * blockDim.x + threadIdx.x;  // 65536
    int b = i >> 10, j = i & 1023;
    g_hstage[(j >> 6) * HBLK + b * 68 + permk(j & 63)] = h0[i];
}

// ---------------------------------------------------------------------------
// Kernel 1: x_proj = A @ W_ih^T + bias.  A fp32 (split on load), W pre-split.
// Tile M=128, N=64, Kchunk=32; 256 threads.
// buf layout (floats): A 0..4608, Bhi 4608..6912, Blo 6912..9216.
// ---------------------------------------------------------------------------
#define XBUF 9216
#define XSMEM (2 * XBUF * 4)             // 73728 B

__global__ __launch_bounds__(256) void xproj_tc_kernel(
    const float* __restrict__ b1, const float* __restrict__ b2)
{
    extern __shared__ float sm[];
    const u32 sbase = smem_u32(sm);
    const int tid = threadIdx.x;
    const int w = tid >> 5, lane = tid & 31;
    const int g = lane >> 2, t = lane & 3;
    const int rm = w >> 1, rn = w & 1;
    const int ntile = blockIdx.x, mtile = blockIdx.y;

    const float4* asrc = reinterpret_cast<const float4*>(
        g_astage + (size_t)(mtile * 32) * ABLK);
    const float4* wsrc = reinterpret_cast<const float4*>(
        g_wihstage + (size_t)(ntile * 32) * WIBLK);

    auto stage = [&](int ck, int buf) {
        u32 d = sbase + (u32)buf * (XBUF * 4);
        const float4* a = asrc + (size_t)ck * (ABLK / 4);
        const float4* ww = wsrc + (size_t)ck * (WIBLK / 4);
        for (int i = tid; i < ABLK / 4; i += 256) cpa16(d + i * 16, a + i);
        for (int i = tid; i < WIBLK / 4; i += 256)
            cpa16(d + ABLK * 4 + i * 16, ww + i);
    };

    float acc[2][4][4];
#pragma unroll
    for (int mt = 0; mt < 2; mt++)
#pragma unroll
        for (int nt = 0; nt < 4; nt++)
#pragma unroll
            for (int e = 0; e < 4; e++) acc[mt][nt][e] = 0.f;

    stage(0, 0);
    CPA_COMMIT();

    for (int ck = 0; ck < 32; ck++) {
        if (ck < 31) { stage(ck + 1, (ck + 1) & 1); CPA_COMMIT(); CPA_WAIT1(); }
        else CPA_WAIT0();
        __syncthreads();

        const float* Af  = sm + (ck & 1) * XBUF;
        const float* Bhi = Af + 4608;
        const float* Blo = Af + 6912;

#pragma unroll
        for (int ks = 0; ks < 4; ks++) {
            int ko = ks * 8 + 2 * t;
            float2 ax[2], ay[2], axh[2], ayh[2];
#pragma unroll
            for (int mt = 0; mt < 2; mt++) {
                int ar = rm * 32 + mt * 16 + g;
                ax[mt] = *reinterpret_cast<const float2*>(&Af[ar * 36 + ko]);
                ay[mt] = *reinterpret_cast<const float2*>(&Af[(ar + 8) * 36 + ko]);
                axh[mt].x = trunc_tf32(ax[mt].x); axh[mt].y = trunc_tf32(ax[mt].y);
                ayh[mt].x = trunc_tf32(ay[mt].x); ayh[mt].y = trunc_tf32(ay[mt].y);
                ax[mt].x -= axh[mt].x; ax[mt].y -= axh[mt].y;   // now lo
                ay[mt].x -= ayh[mt].x; ay[mt].y -= ayh[mt].y;
            }
#pragma unroll
            for (int nt = 0; nt < 4; nt++) {
                int nr = rn * 32 + nt * 8 + g;
                float2 bh = *reinterpret_cast<const float2*>(&Bhi[nr * 36 + ko]);
                float2 bl = *reinterpret_cast<const float2*>(&Blo[nr * 36 + ko]);
#pragma unroll
                for (int mt = 0; mt < 2; mt++) {
                    float* d = acc[mt][nt];
                    mma8(d[0], d[1], d[2], d[3],
                         axh[mt].x, ayh[mt].x, axh[mt].y, ayh[mt].y, bh.x, bh.y);
                    mma8(d[0], d[1], d[2], d[3],
                         ax[mt].x, ay[mt].x, ax[mt].y, ay[mt].y, bh.x, bh.y);
                    mma8(d[0], d[1], d[2], d[3],
                         axh[mt].x, ayh[mt].x, axh[mt].y, ayh[mt].y, bl.x, bl.y);
                }
            }
        }
        __syncthreads();
    }

    const int m0 = mtile * 128, n0 = ntile * 64;
#pragma unroll
    for (int mt = 0; mt < 2; mt++) {
        int row = m0 + rm * 32 + mt * 16 + g;
#pragma unroll
        for (int nt = 0; nt < 4; nt++) {
            int col = n0 + rn * 32 + nt * 8 + 2 * t;
            float bv0 = b1[col] + b2[col];
            float bv1 = b1[col + 1] + b2[col + 1];
            float2 v0 = make_float2(acc[mt][nt][0] + bv0, acc[mt][nt][1] + bv1);
            float2 v1 = make_float2(acc[mt][nt][2] + bv0, acc[mt][nt][3] + bv1);
            *reinterpret_cast<float2*>(g_xproj + (size_t)row * GDIM + col) = v0;
            *reinterpret_cast<float2*>(g_xproj + (size_t)(row + 8) * GDIM + col) = v1;
        }
    }
}

// ---------------------------------------------------------------------------
// Kernel 2: persistent LSTM recurrence. 128 CTAs x 256 threads, all resident.
// CTA ct owns 8 hidden cols jt=ct*8 -> 32 gate cols; loops 512 steps with a
// grid barrier per step. h staged fp32 (split on load), W_hh pre-split.
// buf layout (floats): H 0..4352, Whi 4352..6528, Wlo 6528..8704.
// ---------------------------------------------------------------------------
#define SBUF 8704
#define SSMEM (2 * SBUF * 4)             // 69632 B

__global__ __launch_bounds__(256) void lstm_persistent(
    float* __restrict__ out, const float* __restrict__ c0, int write_tail)
{
    extern __shared__ float sm[];
    const u32 sbase = smem_u32(sm);
    const int tid = threadIdx.x;
    const int w = tid >> 5, lane = tid & 31;
    const int g = lane >> 2, t = lane & 3;
    const int mt = w & 3, nh = w >> 2;
    const int ct = blockIdx.x, jt = ct * 8;

    const float4* wsrc = reinterpret_cast<const float4*>(
        g_whhstage + (size_t)(ct * 16) * WHBLK);

    // cell state in registers (mapping fixed across steps)
    float creg[2];
#pragma unroll
    for (int l = 0; l < 2; l++) {
        int pid = tid + l * 256;
        creg[l] = c0[(pid >> 3) * HDIM + jt + (pid & 7)];
    }

    u64 base_epoch;
    asm volatile("ld.acquire.gpu.global.u64 %0, [%1];"
                 : "=l"(base_epoch) : "l"(&g_bar_epoch) : "memory");

    auto stage_h = [&](const float4* hsrc, int ck, int buf) {
        u32 d = sbase + (u32)buf * (SBUF * 4);
        const float4* h = hsrc + (size_t)ck * (HBLK / 4);
        for (int i = tid; i < HBLK / 4; i += 256) cpa16(d + i * 16, h + i);
    };
    auto stage_w = [&](int ck, int buf) {
        u32 d = sbase + (u32)buf * (SBUF * 4) + HBLK * 4;
        const float4* ww = wsrc + (size_t)ck * (WHBLK / 4);
        for (int i = tid; i < WHBLK / 4; i += 256) cpa16(d + i * 16, ww + i);
    };

    stage_w(0, 0);   // W chunk 0 for step 0 (h side staged after xp prefetch)

    for (int step = 0; step < SEQ; step++) {
        const int rp = step & 1;
        const float4* hsrc = reinterpret_cast<const float4*>(
            g_hstage + (size_t)rp * HPAR);
        float* hdst = g_hstage + (size_t)(rp ^ 1) * HPAR;

        // prefetch this step's xproj slice into registers (used at gate time)
        float2 xp[2][2];
#pragma unroll
        for (int nt = 0; nt < 2; nt++) {
            int c0i = nh * 16 + nt * 8 + 2 * t;
            int gc = (c0i >> 3) * HDIM + jt + (c0i & 7);
            int b0 = mt * 16 + g;
            xp[nt][0] = *reinterpret_cast<const float2*>(
                g_xproj + ((size_t)b0 * SEQ + step) * GDIM + gc);
            xp[nt][1] = *reinterpret_cast<const float2*>(
                g_xproj + ((size_t)(b0 + 8) * SEQ + step) * GDIM + gc);
        }

        stage_h(hsrc, 0, 0);
        CPA_COMMIT();

        float acc[2][4];
#pragma unroll
        for (int nt = 0; nt < 2; nt++)
#pragma unroll
            for (int e = 0; e < 4; e++) acc[nt][e] = 0.f;

        for (int ck = 0; ck < 16; ck++) {
            if (ck < 15) {
                stage_h(hsrc, ck + 1, (ck + 1) & 1);
                stage_w(ck + 1, (ck + 1) & 1);
                CPA_COMMIT(); CPA_WAIT1();
            } else CPA_WAIT0();
            __syncthreads();

            const float* Hf  = sm + (ck & 1) * SBUF;
            const float* Bhi = Hf + 4352;
            const float* Blo = Hf + 6528;

            int ar = mt * 16 + g;
#pragma unroll
            for (int ks = 0; ks < 8; ks++) {
                int ko = ks * 8 + 2 * t;
                float2 ax = *reinterpret_cast<const float2*>(&Hf[ar * 68 + ko]);
                float2 ay = *reinterpret_cast<const float2*>(&Hf[(ar + 8) * 68 + ko]);
                float2 axh, ayh;
                axh.x = trunc_tf32(ax.x); axh.y = trunc_tf32(ax.y);
                ayh.x = trunc_tf32(ay.x); ayh.y = trunc_tf32(ay.y);
                ax.x -= axh.x; ax.y -= axh.y;   // lo
                ay.x -= ayh.x; ay.y -= ayh.y;
#pragma unroll
                for (int nt = 0; nt < 2; nt++) {
                    int nr = nh * 16 + nt * 8 + g;
                    float2 bh = *reinterpret_cast<const float2*>(&Bhi[nr * 68 + ko]);
                    float2 bl = *reinterpret_cast<const float2*>(&Blo[nr * 68 + ko]);
                    float* d = acc[nt];
                    mma8(d[0], d[1], d[2], d[3], axh.x, ayh.x, axh.y, ayh.y, bh.x, bh.y);
                    mma8(d[0], d[1], d[2], d[3], ax.x, ay.x, ax.y, ay.y, bh.x, bh.y);
                    mma8(d[0], d[1], d[2], d[3], axh.x, ayh.x, axh.y, ayh.y, bl.x, bl.y);
                }
            }
            __syncthreads();
        }

        // gate exchange (overlays buf0 H region; 64x33 floats)
        float* gsm = sm;
#pragma unroll
        for (int nt = 0; nt < 2; nt++) {
            int c0i = nh * 16 + nt * 8 + 2 * t;
            int b0 = mt * 16 + g;
            gsm[b0 * 33 + c0i]           = acc[nt][0] + xp[nt][0].x;
            gsm[b0 * 33 + c0i + 1]       = acc[nt][1] + xp[nt][0].y;
            gsm[(b0 + 8) * 33 + c0i]     = acc[nt][2] + xp[nt][1].x;
            gsm[(b0 + 8) * 33 + c0i + 1] = acc[nt][3] + xp[nt][1].y;
        }
        __syncthreads();

        // pointwise update + write next-step h stage (fp32)
#pragma unroll
        for (int l = 0; l < 2; l++) {
            int pid = tid + l * 256;
            int b = pid >> 3, jj = pid & 7, j = jt + jj;
            float ig = gsm[b * 33 + jj];
            float fg = gsm[b * 33 + 8 + jj];
            float gg = gsm[b * 33 + 16 + jj];
            float og = gsm[b * 33 + 24 + jj];
            float cn = sigmoidf_(fg) * creg[l] + sigmoidf_(ig) * tanhf(gg);
            float h = sigmoidf_(og) * tanhf(cn);
            creg[l] = cn;
            out[(size_t)b * SEQ * HDIM + (size_t)step * HDIM + j] = h;
            hdst[(j >> 6) * HBLK + b * 68 + permk(j & 63)] = h;
            if (write_tail && step == SEQ - 1) {
                float* tail = out + (size_t)SEQ * BATCH * HDIM;
                tail[b * HDIM + j] = h;
                tail[BATCH * HDIM + b * HDIM + j] = cn;
            }
        }

        if (step < SEQ - 1) {
            stage_w(0, 0);                 // W for next step (pre-barrier, private)
            gbar(base_epoch + step + 1);   // h[rp^1] now globally complete
        }
    }
}

// ---------------------------------------------------------------------------
// Launch
// ---------------------------------------------------------------------------
extern "C" void kernel_launch(void* const* d_in, const int* in_sizes, int n_in,
                              void* d_out, int out_size) {
    const float* inp  = (const float*)d_in[0];
    const float* h0   = (const float*)d_in[1];
    const float* c0   = (const float*)d_in[2];
    const float* W_ih = (const float*)d_in[3];
    const float* W_hh = (const float*)d_in[4];
    const float* b_ih = (const float*)d_in[5];
    const float* b_hh = (const float*)d_in[6];
    float* out = (float*)d_out;

    cudaFuncSetAttribute(xproj_tc_kernel,
                         cudaFuncAttributeMaxDynamicSharedMemorySize, XSMEM);
    cudaFuncSetAttribute(lstm_persistent,
                         cudaFuncAttributeMaxDynamicSharedMemorySize, SSMEM);

    split_a_kernel<<<SEQ * BATCH * INDIM / 1024, 1024>>>(inp);
    split_wih_kernel<<<2048, 512>>>(W_ih);
    split_whh_kernel<<<2048, 512>>>(W_hh);
    init_state_kernel<<<64, 1024>>>(h0);

    dim3 gx(GDIM / 64, (SEQ * BATCH) / 128);
    xproj_tc_kernel<<<gx, 256, XSMEM>>>(b_ih, b_hh);

    int tail = (out_size >= SEQ * BATCH * HDIM + 2 * BATCH * HDIM) ? 1 : 0;
    lstm_persistent<<<128, 256, SSMEM>>>(out, c0, tail);
}

// round 9
// speedup vs baseline: 1.6568x; 1.0563x over previous
#include <cuda_runtime.h>
#include <cuda_bf16.h>
#include <math.h>
#include <string.h>

#define SEQ   512
#define BATCH 64
#define INDIM 1024
#define HDIM  1024
#define GDIM  4096   // 4*H

typedef unsigned int u32;
typedef unsigned long long u64;

// ---------------------------------------------------------------------------
// Gmem scratch (all staged operands are packed bf16 hi/lo planes, u32 granules
// = bf16x2 for k-pair (2q, 2q+1), permuted so fragments load as LDS.64)
// ---------------------------------------------------------------------------
__device__ float g_xproj[(size_t)SEQ * BATCH * GDIM];              // 512 MB

// A (inp) for xproj: per (mtile 0..255, ck 0..15 of K64): [hi 128x40][lo 128x40]
#define AB_U32 (2 * 128 * 40)            // 10240 u32
__device__ u32 g_ast[(size_t)256 * 16 * AB_U32];                   // 168 MB

// W_ih: per (ntile 0..63, ck 0..15): [hi 64x40][lo 64x40]
#define WI_U32 (2 * 64 * 40)             // 5120 u32
__device__ u32 g_wih2[(size_t)64 * 16 * WI_U32];                   // 21 MB

// W_hh: per (ct 0..127, ck 0..7 of K128): [hi 32x72][lo 32x72]
#define WH_U32 (2 * 32 * 72)             // 4608 u32
__device__ u32 g_whh2[(size_t)128 * 8 * WH_U32];                   // 19 MB

// h (parity double buffer): per (par, ck 0..7): [hi 64x72][lo 64x72]
#define HB_U32 (2 * 64 * 72)             // 9216 u32
#define HPAR   (8 * HB_U32)
__device__ u32 g_hst[2 * HPAR];

__device__ float g_c_unused;             // (cell state lives in registers)

// Grid barrier flags (monotonic across graph replays; never reset)
__device__ u32 g_flags[128];

// ---------------------------------------------------------------------------
// Helpers
// ---------------------------------------------------------------------------
// RN bf16 split of a k-pair into packed hi and lo u32 granules.
__device__ __forceinline__ void bf16_split2(float v0, float v1, u32& hi, u32& lo) {
    __nv_bfloat162 h2 = __floats2bfloat162_rn(v0, v1);
    float r0 = v0 - __low2float(h2);
    float r1 = v1 - __high2float(h2);
    __nv_bfloat162 l2 = __floats2bfloat162_rn(r0, r1);
    memcpy(&hi, &h2, 4);
    memcpy(&lo, &l2, 4);
}

__device__ __forceinline__ void mma16(float* d, u32 a0, u32 a1, u32 a2, u32 a3,
                                      u32 b0, u32 b1) {
    asm volatile(
        "mma.sync.aligned.m16n8k16.row.col.f32.bf16.bf16.f32 "
        "{%0,%1,%2,%3}, {%4,%5,%6,%7}, {%8,%9}, {%0,%1,%2,%3};"
        : "+f"(d[0]), "+f"(d[1]), "+f"(d[2]), "+f"(d[3])
        : "r"(a0), "r"(a1), "r"(a2), "r"(a3), "r"(b0), "r"(b1));
}

// granule permutation within each 8-granule (16-k) group: pairs (q, q+4) adjacent
__device__ __forceinline__ int permq(int q) {
    return (q & ~7) | ((q & 3) << 1) | ((q >> 2) & 1);
}

__device__ __forceinline__ float sigmoidf_(float x) {
    return 1.f / (1.f + expf(-x));
}

__device__ __forceinline__ u32 smem_u32(const void* p) {
    u32 a;
    asm("{ .reg .u64 t; cvta.to.shared.u64 t, %1; cvt.u32.u64 %0, t; }"
        : "=r"(a) : "l"(p));
    return a;
}

__device__ __forceinline__ void cpa16(u32 dst, const float4* src) {
    asm volatile("cp.async.cg.shared.global [%0], [%1], 16;"
                 :: "r"(dst), "l"(src));
}
#define CPA_COMMIT() asm volatile("cp.async.commit_group;" ::: "memory")
#define CPA_WAIT1()  asm volatile("cp.async.wait_group 1;" ::: "memory")
#define CPA_WAIT0()  asm volatile("cp.async.wait_group 0;" ::: "memory")

// Grid-wide barrier: per-CTA release flags + one warp polls all 128.
__device__ __forceinline__ void gbar2(u32 target) {
    __threadfence();
    __syncthreads();
    if (threadIdx.x < 32) {
        if (threadIdx.x == 0) {
            asm volatile("st.release.gpu.global.u32 [%0], %1;"
                         :: "l"(&g_flags[blockIdx.x]), "r"(target) : "memory");
        }
        const u32* f = &g_flags[threadIdx.x * 4];
        for (;;) {
            u32 v0, v1, v2, v3;
            asm volatile("ld.acquire.gpu.global.u32 %0, [%1];" : "=r"(v0) : "l"(f + 0) : "memory");
            asm volatile("ld.acquire.gpu.global.u32 %0, [%1];" : "=r"(v1) : "l"(f + 1) : "memory");
            asm volatile("ld.acquire.gpu.global.u32 %0, [%1];" : "=r"(v2) : "l"(f + 2) : "memory");
            asm volatile("ld.acquire.gpu.global.u32 %0, [%1];" : "=r"(v3) : "l"(f + 3) : "memory");
            bool ok = (v0 >= target) && (v1 >= target) && (v2 >= target) && (v3 >= target);
            if (__ballot_sync(0xffffffffu, ok) == 0xffffffffu) break;
            __nanosleep(32);
        }
    }
    __syncthreads();
}

// ---------------------------------------------------------------------------
// One-time split/permute prep
// ---------------------------------------------------------------------------
__global__ void split_a_kernel(const float* __restrict__ A) {
    int gid = blockIdx.x * 256 + threadIdx.x;        // 16.78M granules
    int m = gid >> 9, qg = gid & 511;
    float2 v = *reinterpret_cast<const float2*>(A + (size_t)m * INDIM + qg * 2);
    u32 hi, lo;
    bf16_split2(v.x, v.y, hi, lo);
    int ck = qg >> 5, pq = permq(qg & 31);
    u32* dst = g_ast + (size_t)((m >> 7) * 16 + ck) * AB_U32 + (m & 127) * 40 + pq;
    dst[0] = hi;
    dst[128 * 40] = lo;
}

__global__ void split_wih_kernel(const float* __restrict__ W) {
    int gid = blockIdx.x * 256 + threadIdx.x;        // 2.1M granules
    int n = gid >> 9, qg = gid & 511;
    float2 v = *reinterpret_cast<const float2*>(W + (size_t)n * INDIM + qg * 2);
    u32 hi, lo;
    bf16_split2(v.x, v.y, hi, lo);
    int ck = qg >> 5, pq = permq(qg & 31);
    u32* dst = g_wih2 + (size_t)((n >> 6) * 16 + ck) * WI_U32 + (n & 63) * 40 + pq;
    dst[0] = hi;
    dst[64 * 40] = lo;
}

__global__ void split_whh_kernel(const float* __restrict__ W) {
    int gid = blockIdx.x * 256 + threadIdx.x;        // 2.1M granules
    int n = gid >> 9, qg = gid & 511;                // n = gate row 0..4095
    float2 v = *reinterpret_cast<const float2*>(W + (size_t)n * HDIM + qg * 2);
    u32 hi, lo;
    bf16_split2(v.x, v.y, hi, lo);
    int gg = n >> 10, j = n & 1023;
    int ct = j >> 3, r = gg * 8 + (j & 7);
    int ck = qg >> 6, pq = permq(qg & 63);
    u32* dst = g_whh2 + (size_t)(ct * 8 + ck) * WH_U32 + r * 72 + pq;
    dst[0] = hi;
    dst[32 * 72] = lo;
}

__global__ void init_state_kernel(const float* __restrict__ h0) {
    int gid = blockIdx.x * 256 + threadIdx.x;        // 32768 granules
    int b = gid >> 9, qg = gid & 511;
    float2 v = *reinterpret_cast<const float2*>(h0 + (size_t)b * HDIM + qg * 2);
    u32 hi, lo;
    bf16_split2(v.x, v.y, hi, lo);
    int ck = qg >> 6, pq = permq(qg & 63);
    u32* dst = g_hst + (size_t)ck * HB_U32 + b * 72 + pq;
    dst[0] = hi;
    dst[64 * 72] = lo;
}

// ---------------------------------------------------------------------------
// Kernel 1: x_proj = A @ W_ih^T + bias  [bf16x3 HMMA]
// Tile M=128, N=64, Kchunk=64 (16 chunks); 256 threads.
// buf (u32): Ahi 0 (128x40), Alo 5120, Whi 10240 (64x40), Wlo 12800. = 15360
// ---------------------------------------------------------------------------
#define XBUF 15360
#define XSMEM (2 * XBUF * 4)             // 122880 B

__global__ __launch_bounds__(256) void xproj_tc_kernel(
    const float* __restrict__ b1, const float* __restrict__ b2)
{
    extern __shared__ u32 smu[];
    const u32 sbase = smem_u32(smu);
    const int tid = threadIdx.x;
    const int w = tid >> 5, lane = tid & 31;
    const int g = lane >> 2, t = lane & 3;
    const int rm = w >> 1, rn = w & 1;
    const int ntile = blockIdx.x, mtile = blockIdx.y;

    const float4* asrc = reinterpret_cast<const float4*>(
        g_ast + (size_t)(mtile * 16) * AB_U32);
    const float4* wsrc = reinterpret_cast<const float4*>(
        g_wih2 + (size_t)(ntile * 16) * WI_U32);

    auto stage = [&](int ck, int buf) {
        u32 d = sbase + (u32)buf * (XBUF * 4);
        const float4* a = asrc + (size_t)ck * (AB_U32 / 4);
        const float4* ww = wsrc + (size_t)ck * (WI_U32 / 4);
        for (int i = tid; i < AB_U32 / 4; i += 256) cpa16(d + i * 16, a + i);
        for (int i = tid; i < WI_U32 / 4; i += 256)
            cpa16(d + AB_U32 * 4 + i * 16, ww + i);
    };

    float acc[2][4][4];
#pragma unroll
    for (int mt = 0; mt < 2; mt++)
#pragma unroll
        for (int nt = 0; nt < 4; nt++)
#pragma unroll
            for (int e = 0; e < 4; e++) acc[mt][nt][e] = 0.f;

    stage(0, 0);
    CPA_COMMIT();

    for (int ck = 0; ck < 16; ck++) {
        if (ck < 15) { stage(ck + 1, (ck + 1) & 1); CPA_COMMIT(); CPA_WAIT1(); }
        else CPA_WAIT0();
        __syncthreads();

        const u32* B0 = smu + (ck & 1) * XBUF;

#pragma unroll
        for (int ks = 0; ks < 4; ks++) {
            int ko = ks * 8 + 2 * t;
            uint2 axh[2], ayh[2], axl[2], ayl[2];
#pragma unroll
            for (int mt = 0; mt < 2; mt++) {
                int ar = rm * 32 + mt * 16 + g;
                axh[mt] = *reinterpret_cast<const uint2*>(&B0[ar * 40 + ko]);
                ayh[mt] = *reinterpret_cast<const uint2*>(&B0[(ar + 8) * 40 + ko]);
                axl[mt] = *reinterpret_cast<const uint2*>(&B0[5120 + ar * 40 + ko]);
                ayl[mt] = *reinterpret_cast<const uint2*>(&B0[5120 + (ar + 8) * 40 + ko]);
            }
#pragma unroll
            for (int nt = 0; nt < 4; nt++) {
                int nr = rn * 32 + nt * 8 + g;
                uint2 bh = *reinterpret_cast<const uint2*>(&B0[10240 + nr * 40 + ko]);
                uint2 bl = *reinterpret_cast<const uint2*>(&B0[12800 + nr * 40 + ko]);
#pragma unroll
                for (int mt = 0; mt < 2; mt++) {
                    float* d = acc[mt][nt];
                    mma16(d, axh[mt].x, ayh[mt].x, axh[mt].y, ayh[mt].y, bh.x, bh.y);
                    mma16(d, axl[mt].x, ayl[mt].x, axl[mt].y, ayl[mt].y, bh.x, bh.y);
                    mma16(d, axh[mt].x, ayh[mt].x, axh[mt].y, ayh[mt].y, bl.x, bl.y);
                }
            }
        }
        __syncthreads();
    }

    const int m0 = mtile * 128, n0 = ntile * 64;
#pragma unroll
    for (int mt = 0; mt < 2; mt++) {
        int row = m0 + rm * 32 + mt * 16 + g;
#pragma unroll
        for (int nt = 0; nt < 4; nt++) {
            int col = n0 + rn * 32 + nt * 8 + 2 * t;
            float bv0 = b1[col] + b2[col];
            float bv1 = b1[col + 1] + b2[col + 1];
            float2 v0 = make_float2(acc[mt][nt][0] + bv0, acc[mt][nt][1] + bv1);
            float2 v1 = make_float2(acc[mt][nt][2] + bv0, acc[mt][nt][3] + bv1);
            *reinterpret_cast<float2*>(g_xproj + (size_t)row * GDIM + col) = v0;
            *reinterpret_cast<float2*>(g_xproj + (size_t)(row + 8) * GDIM + col) = v1;
        }
    }
}

// ---------------------------------------------------------------------------
// Kernel 2: persistent LSTM recurrence [bf16x3 HMMA]. 128 CTAs x 256 threads.
// CTA ct owns 8 hidden cols -> 32 gate cols; M=64, N=32, K=1024, Kchunk=128.
// buf (u32): Hhi 0 (64x72), Hlo 4608, Whi 9216 (32x72), Wlo 11520. = 13824
// ---------------------------------------------------------------------------
#define SBUF 13824
#define SSMEM (2 * SBUF * 4)             // 110592 B

__global__ __launch_bounds__(256) void lstm_persistent(
    float* __restrict__ out, const float* __restrict__ c0, int write_tail)
{
    extern __shared__ u32 smu[];
    const u32 sbase = smem_u32(smu);
    const int tid = threadIdx.x;
    const int w = tid >> 5, lane = tid & 31;
    const int g = lane >> 2, t = lane & 3;
    const int mt = w & 3, nh = w >> 2;
    const int ct = blockIdx.x, jt = ct * 8;

    const float4* wsrc = reinterpret_cast<const float4*>(
        g_whh2 + (size_t)(ct * 8) * WH_U32);

    // cell state in registers
    float creg[2];
#pragma unroll
    for (int l = 0; l < 2; l++) {
        int pid = tid + l * 256;
        creg[l] = c0[(pid >> 3) * HDIM + jt + (pid & 7)];
    }

    __shared__ u32 s_base;
    if (tid == 0) {
        u32 b;
        asm volatile("ld.acquire.gpu.global.u32 %0, [%1];"
                     : "=r"(b) : "l"(&g_flags[blockIdx.x]) : "memory");
        s_base = b;
    }
    __syncthreads();
    const u32 base_epoch = s_base;

    auto stage = [&](const float4* hsrc, int ck, int buf) {
        u32 d = sbase + (u32)buf * (SBUF * 4);
        const float4* h = hsrc + (size_t)ck * (HB_U32 / 4);
        const float4* ww = wsrc + (size_t)ck * (WH_U32 / 4);
        for (int i = tid; i < HB_U32 / 4; i += 256) cpa16(d + i * 16, h + i);
        for (int i = tid; i < WH_U32 / 4; i += 256)
            cpa16(d + HB_U32 * 4 + i * 16, ww + i);
    };

    for (int step = 0; step < SEQ; step++) {
        const int rp = step & 1;
        const float4* hsrc = reinterpret_cast<const float4*>(
            g_hst + (size_t)rp * HPAR);
        u32* hdst = g_hst + (size_t)(rp ^ 1) * HPAR;

        // prefetch this step's xproj slice
        float2 xp[2][2];
#pragma unroll
        for (int nt = 0; nt < 2; nt++) {
            int c0i = nh * 16 + nt * 8 + 2 * t;
            int gc = (c0i >> 3) * HDIM + jt + (c0i & 7);
            int b0 = mt * 16 + g;
            xp[nt][0] = *reinterpret_cast<const float2*>(
                g_xproj + ((size_t)b0 * SEQ + step) * GDIM + gc);
            xp[nt][1] = *reinterpret_cast<const float2*>(
                g_xproj + ((size_t)(b0 + 8) * SEQ + step) * GDIM + gc);
        }

        stage(hsrc, 0, 0);
        CPA_COMMIT();

        float acc[2][4];
#pragma unroll
        for (int nt = 0; nt < 2; nt++)
#pragma unroll
            for (int e = 0; e < 4; e++) acc[nt][e] = 0.f;

        for (int ck = 0; ck < 8; ck++) {
            if (ck < 7) { stage(hsrc, ck + 1, (ck + 1) & 1); CPA_COMMIT(); CPA_WAIT1(); }
            else CPA_WAIT0();
            __syncthreads();

            const u32* B0 = smu + (ck & 1) * SBUF;
            int ar = mt * 16 + g;
#pragma unroll
            for (int ks = 0; ks < 8; ks++) {
                int ko = ks * 8 + 2 * t;
                uint2 axh = *reinterpret_cast<const uint2*>(&B0[ar * 72 + ko]);
                uint2 ayh = *reinterpret_cast<const uint2*>(&B0[(ar + 8) * 72 + ko]);
                uint2 axl = *reinterpret_cast<const uint2*>(&B0[4608 + ar * 72 + ko]);
                uint2 ayl = *reinterpret_cast<const uint2*>(&B0[4608 + (ar + 8) * 72 + ko]);
#pragma unroll
                for (int nt = 0; nt < 2; nt++) {
                    int nr = nh * 16 + nt * 8 + g;
                    uint2 bh = *reinterpret_cast<const uint2*>(&B0[9216 + nr * 72 + ko]);
                    uint2 bl = *reinterpret_cast<const uint2*>(&B0[11520 + nr * 72 + ko]);
                    float* d = acc[nt];
                    mma16(d, axh.x, ayh.x, axh.y, ayh.y, bh.x, bh.y);
                    mma16(d, axl.x, ayl.x, axl.y, ayl.y, bh.x, bh.y);
                    mma16(d, axh.x, ayh.x, axh.y, ayh.y, bl.x, bl.y);
                }
            }
            __syncthreads();
        }

        // gate exchange (overlays buf0; 64x33 floats)
        float* gsm = reinterpret_cast<float*>(smu);
#pragma unroll
        for (int nt = 0; nt < 2; nt++) {
            int c0i = nh * 16 + nt * 8 + 2 * t;
            int b0 = mt * 16 + g;
            gsm[b0 * 33 + c0i]           = acc[nt][0] + xp[nt][0].x;
            gsm[b0 * 33 + c0i + 1]       = acc[nt][1] + xp[nt][0].y;
            gsm[(b0 + 8) * 33 + c0i]     = acc[nt][2] + xp[nt][1].x;
            gsm[(b0 + 8) * 33 + c0i + 1] = acc[nt][3] + xp[nt][1].y;
        }
        __syncthreads();

        // pointwise update + write next-step h stage (bf16 hi/lo planes)
#pragma unroll
        for (int l = 0; l < 2; l++) {
            int pid = tid + l * 256;
            int b = pid >> 3, jj = pid & 7, j = jt + jj;
            float ig = gsm[b * 33 + jj];
            float fg = gsm[b * 33 + 8 + jj];
            float gg = gsm[b * 33 + 16 + jj];
            float og = gsm[b * 33 + 24 + jj];
            float cn = sigmoidf_(fg) * creg[l] + sigmoidf_(ig) * tanhf(gg);
            float h = sigmoidf_(og) * tanhf(cn);
            creg[l] = cn;
            out[(size_t)b * SEQ * HDIM + (size_t)step * HDIM + j] = h;

            __nv_bfloat16 hb = __float2bfloat16(h);
            float rl = h - __bfloat162float(hb);
            __nv_bfloat16 lb = __float2bfloat16(rl);
            int ck = j >> 7, pq = permq((j & 127) >> 1);
            u32* blk = hdst + (size_t)ck * HB_U32;
            unsigned short* hp = reinterpret_cast<unsigned short*>(blk + b * 72 + pq);
            unsigned short* lp = reinterpret_cast<unsigned short*>(blk + 64 * 72 + b * 72 + pq);
            hp[j & 1] = __bfloat16_as_ushort(hb);
            lp[j & 1] = __bfloat16_as_ushort(lb);

            if (write_tail && step == SEQ - 1) {
                float* tail = out + (size_t)SEQ * BATCH * HDIM;
                tail[b * HDIM + j] = h;
                tail[BATCH * HDIM + b * HDIM + j] = cn;
            }
        }

        if (step < SEQ - 1) gbar2(base_epoch + step + 1);
    }
}

// ---------------------------------------------------------------------------
// Launch
// ---------------------------------------------------------------------------
extern "C" void kernel_launch(void* const* d_in, const int* in_sizes, int n_in,
                              void* d_out, int out_size) {
    const float* inp  = (const float*)d_in[0];
    const float* h0   = (const float*)d_in[1];
    const float* c0   = (const float*)d_in[2];
    const float* W_ih = (const float*)d_in[3];
    const float* W_hh = (const float*)d_in[4];
    const float* b_ih = (const float*)d_in[5];
    const float* b_hh = (const float*)d_in[6];
    float* out = (float*)d_out;

    cudaFuncSetAttribute(xproj_tc_kernel,
                         cudaFuncAttributeMaxDynamicSharedMemorySize, XSMEM);
    cudaFuncSetAttribute(lstm_persistent,
                         cudaFuncAttributeMaxDynamicSharedMemorySize, SSMEM);

    split_a_kernel<<<SEQ * BATCH * INDIM / 512, 256>>>(inp);
    split_wih_kernel<<<GDIM * INDIM / 512, 256>>>(W_ih);
    split_whh_kernel<<<GDIM * HDIM / 512, 256>>>(W_hh);
    init_state_kernel<<<BATCH * HDIM / 512, 256>>>(h0);

    dim3 gx(GDIM / 64, (SEQ * BATCH) / 128);
    xproj_tc_kernel<<<gx, 256, XSMEM>>>(b_ih, b_hh);

    int tail = (out_size >= SEQ * BATCH * HDIM + 2 * BATCH * HDIM) ? 1 : 0;
    lstm_persistent<<<128, 256, SSMEM>>>(out, c0, tail);
}